// round 2
// baseline (speedup 1.0000x reference)
#include <cuda_runtime.h>
#include <cstdint>

#define N_TOK 8192
#define DIM   2048
#define NEXP  8

#define BM 128
#define BN 128
#define BK 32
#define LDS_W 36   // smem row stride in words: 36*4=144B (16B aligned), banks 4r+k span all 32

// ---------------- scratch (no allocations allowed) ----------------
__device__ int   g_cnt[NEXP];
__device__ int   g_idx[NEXP * N_TOK];
__device__ float g_gate[N_TOK];

// ---------------- helpers ----------------
__device__ __forceinline__ uint32_t f2tf(float f) {
    uint32_t u;
    asm("cvt.rna.tf32.f32 %0, %1;" : "=r"(u) : "f"(f));
    return u;
}

__device__ __forceinline__ void mma_tf32(float (&c)[4], const uint32_t (&a)[4],
                                         const uint32_t (&b)[2]) {
    asm volatile(
        "mma.sync.aligned.m16n8k8.row.col.f32.tf32.tf32.f32 "
        "{%0,%1,%2,%3}, {%4,%5,%6,%7}, {%8,%9}, {%0,%1,%2,%3};"
        : "+f"(c[0]), "+f"(c[1]), "+f"(c[2]), "+f"(c[3])
        : "r"(a[0]), "r"(a[1]), "r"(a[2]), "r"(a[3]), "r"(b[0]), "r"(b[1]));
}

// ---------------- init: zero counters + the loss-scalar tail ----------------
__global__ void init_kernel(float* out_tail, int tail_n) {
    int t = blockIdx.x * blockDim.x + threadIdx.x;
    if (t < NEXP) g_cnt[t] = 0;
    if (t < tail_n) out_tail[t] = 0.0f;
}

// ---------------- router: warp-per-token, 8 tokens/block ----------------
// logits[e] = x . router_w[e] + rb[e]; argmax (first max, matching jnp.argmax);
// gate = softmax max prob = 1/sum(exp(l - lmax)). Build per-expert gather lists.
__global__ void __launch_bounds__(256) router_kernel(
    const float* __restrict__ x, const float* __restrict__ rw,
    const float* __restrict__ rb)
{
    __shared__ float s_w[NEXP][256];
    __shared__ float s_x[8][256];
    const int tid  = threadIdx.x;
    const int wid  = tid >> 5, lane = tid & 31;
    const int tok0 = blockIdx.x * 8;

    float acc[NEXP];
#pragma unroll
    for (int e = 0; e < NEXP; e++) acc[e] = 0.f;

    for (int ch = 0; ch < DIM / 256; ch++) {
        __syncthreads();  // previous chunk's readers done
#pragma unroll
        for (int i = 0; i < 2; i++) {
            int f = tid + i * 256;            // 0..511 (512 float4 total)
            int r = f >> 6, c = f & 63;       // 64 float4 per 256-float row
            ((float4*)&s_w[r][0])[c] =
                *(const float4*)(rw + (size_t)r * DIM + ch * 256 + c * 4);
            ((float4*)&s_x[r][0])[c] =
                *(const float4*)(x + (size_t)(tok0 + r) * DIM + ch * 256 + c * 4);
        }
        __syncthreads();
#pragma unroll
        for (int j = 0; j < 2; j++) {
            float4 xv = ((const float4*)&s_x[wid][0])[j * 32 + lane];
#pragma unroll
            for (int e = 0; e < NEXP; e++) {
                float4 wv = ((const float4*)&s_w[e][0])[j * 32 + lane];
                acc[e] += xv.x * wv.x + xv.y * wv.y + xv.z * wv.z + xv.w * wv.w;
            }
        }
    }

#pragma unroll
    for (int e = 0; e < NEXP; e++) {
        float v = acc[e];
#pragma unroll
        for (int o = 16; o > 0; o >>= 1) v += __shfl_xor_sync(0xffffffffu, v, o);
        acc[e] = v;
    }

    if (lane == 0) {
        int tok = tok0 + wid;
        float l[NEXP];
        float best = -3.4e38f;
        int bi = 0;
#pragma unroll
        for (int e = 0; e < NEXP; e++) {
            l[e] = acc[e] + rb[e];
            if (l[e] > best) { best = l[e]; bi = e; }   // strict >: first max wins
        }
        float denom = 0.f;
#pragma unroll
        for (int e = 0; e < NEXP; e++) denom += expf(l[e] - best);
        g_gate[tok] = 1.0f / denom;
        int pos = atomicAdd(&g_cnt[bi], 1);
        g_idx[bi * N_TOK + pos] = tok;
    }
}

// ---------------- grouped expert GEMM, TF32 mma.sync ----------------
// out[tok, n] = (sum_k x[tok,k] * W_e[n,k] + b_e[n]) * gate[tok], tok gathered per expert.
__global__ void __launch_bounds__(256) moe_gemm_kernel(
    const float* __restrict__ x, const float* __restrict__ ew,
    const float* __restrict__ eb, float* __restrict__ out)
{
    const int e   = blockIdx.z;
    const int cnt = g_cnt[e];
    const int m0  = blockIdx.y * BM;
    if (m0 >= cnt) return;
    const int n0  = blockIdx.x * BN;

    __shared__ uint32_t As[BM][LDS_W];
    __shared__ uint32_t Bs[BN][LDS_W];

    const int tid  = threadIdx.x;
    const int lane = tid & 31, wid = tid >> 5;
    const int wm   = wid & 3, wn = wid >> 2;   // 4x2 warp grid, warp tile 32x64
    const int gid  = lane >> 2, tig = lane & 3;

    const float* wbase = ew + (size_t)e * DIM * DIM;

    // per-thread source pointers (row/col fixed, k advances)
    const float* aptr[4];
    const float* bptr[4];
#pragma unroll
    for (int i = 0; i < 4; i++) {
        int f = tid + i * 256;
        int r = f >> 3;              // 8 float4 per 32-float row
        int c = (f & 7) << 2;
        int row = m0 + r;
        aptr[i] = (row < cnt) ? (x + (size_t)g_idx[e * N_TOK + row] * DIM + c) : nullptr;
        bptr[i] = wbase + (size_t)(n0 + r) * DIM + c;
    }

    float4 stA[4], stB[4];

    // prologue: tile 0
#pragma unroll
    for (int i = 0; i < 4; i++) {
        stA[i] = aptr[i] ? *(const float4*)(aptr[i]) : make_float4(0.f, 0.f, 0.f, 0.f);
        stB[i] = *(const float4*)(bptr[i]);
    }
#pragma unroll
    for (int i = 0; i < 4; i++) {
        int f = tid + i * 256;
        int r = f >> 3, c = (f & 7) << 2;
        *(uint4*)&As[r][c] = make_uint4(f2tf(stA[i].x), f2tf(stA[i].y), f2tf(stA[i].z), f2tf(stA[i].w));
        *(uint4*)&Bs[r][c] = make_uint4(f2tf(stB[i].x), f2tf(stB[i].y), f2tf(stB[i].z), f2tf(stB[i].w));
    }
    __syncthreads();

    float acc[2][8][4];
#pragma unroll
    for (int mi = 0; mi < 2; mi++)
#pragma unroll
        for (int ni = 0; ni < 8; ni++)
#pragma unroll
            for (int q = 0; q < 4; q++) acc[mi][ni][q] = 0.f;

    const int KT = DIM / BK;
    for (int kt = 0; kt < KT; kt++) {
        const int nk = (kt + 1) * BK;
        const bool more = nk < DIM;
        if (more) {
#pragma unroll
            for (int i = 0; i < 4; i++) {
                stA[i] = aptr[i] ? *(const float4*)(aptr[i] + nk) : make_float4(0.f, 0.f, 0.f, 0.f);
                stB[i] = *(const float4*)(bptr[i] + nk);
            }
        }
        // compute on current smem tile
#pragma unroll
        for (int kk = 0; kk < BK; kk += 8) {
            uint32_t afr[2][4];
            uint32_t bfr[8][2];
#pragma unroll
            for (int mi = 0; mi < 2; mi++) {
                int r = wm * 32 + mi * 16 + gid;
                afr[mi][0] = As[r][kk + tig];
                afr[mi][1] = As[r + 8][kk + tig];
                afr[mi][2] = As[r][kk + tig + 4];
                afr[mi][3] = As[r + 8][kk + tig + 4];
            }
#pragma unroll
            for (int ni = 0; ni < 8; ni++) {
                int c = wn * 64 + ni * 8 + gid;
                bfr[ni][0] = Bs[c][kk + tig];
                bfr[ni][1] = Bs[c][kk + tig + 4];
            }
#pragma unroll
            for (int mi = 0; mi < 2; mi++)
#pragma unroll
                for (int ni = 0; ni < 8; ni++)
                    mma_tf32(acc[mi][ni], afr[mi], bfr[ni]);
        }
        __syncthreads();
        if (more) {
#pragma unroll
            for (int i = 0; i < 4; i++) {
                int f = tid + i * 256;
                int r = f >> 3, c = (f & 7) << 2;
                *(uint4*)&As[r][c] = make_uint4(f2tf(stA[i].x), f2tf(stA[i].y), f2tf(stA[i].z), f2tf(stA[i].w));
                *(uint4*)&Bs[r][c] = make_uint4(f2tf(stB[i].x), f2tf(stB[i].y), f2tf(stB[i].z), f2tf(stB[i].w));
            }
            __syncthreads();
        }
    }

    // epilogue: +bias, *gate, scatter to token rows
#pragma unroll
    for (int mi = 0; mi < 2; mi++) {
#pragma unroll
        for (int h = 0; h < 2; h++) {
            int r   = wm * 32 + mi * 16 + h * 8 + gid;
            int row = m0 + r;
            if (row >= cnt) continue;
            int tok    = g_idx[e * N_TOK + row];
            float gate = g_gate[tok];
            float* orow       = out + (size_t)tok * DIM + n0 + wn * 64;
            const float* brow = eb + (size_t)e * DIM + n0 + wn * 64;
#pragma unroll
            for (int ni = 0; ni < 8; ni++) {
                int c = ni * 8 + tig * 2;
                float v0 = (acc[mi][ni][h * 2 + 0] + brow[c]) * gate;
                float v1 = (acc[mi][ni][h * 2 + 1] + brow[c + 1]) * gate;
                *(float2*)(orow + c) = make_float2(v0, v1);
            }
        }
    }
}

// ---------------- launch ----------------
extern "C" void kernel_launch(void* const* d_in, const int* in_sizes, int n_in,
                              void* d_out, int out_size) {
    const float* x  = (const float*)d_in[0];   // [8192, 2048]
    const float* ew = (const float*)d_in[1];   // [8, 2048, 2048]
    const float* eb = (const float*)d_in[2];   // [8, 2048]
    const float* rw = (const float*)d_in[3];   // [8, 2048]
    const float* rb = (const float*)d_in[4];   // [8]
    float* out = (float*)d_out;

    int tail = out_size - N_TOK * DIM;         // loss scalar (and any padding)
    if (tail < 0) tail = 0;
    init_kernel<<<1, 256>>>(out + N_TOK * DIM, tail);

    router_kernel<<<N_TOK / 8, 256>>>(x, rw, rb);

    dim3 grid(DIM / BN, N_TOK / BM, NEXP);
    moe_gemm_kernel<<<grid, 256>>>(x, ew, eb, out);
}

// round 4
// speedup vs baseline: 1.1536x; 1.1536x over previous
#include <cuda_runtime.h>
#include <cstdint>

#define N_TOK 8192
#define DIM   2048
#define NEXP  8

// GEMM tiling
#define BM 128
#define BN 128
#define BK 32
#define KT (DIM / BK)                      // 64 k-tiles
#define ST 4                               // pipeline stages
#define A_BYTES (BM * 128)                 // 16 KB (128 rows x 32 tf32)
#define B_BYTES (BN * 128)                 // 16 KB
#define STAGE_BYTES (A_BYTES + B_BYTES)    // 32 KB
#define CTRL 1024
#define SMEM_DYN (1024 + CTRL + ST * STAGE_BYTES)

// ---------------- scratch ----------------
__device__ int   g_cnt[NEXP];
__device__ int   g_idx[NEXP * N_TOK];
__device__ float g_gate[N_TOK];

// ---------------- helpers ----------------
__device__ __forceinline__ uint32_t smem_u32(const void* p) {
    uint32_t a;
    asm("{ .reg .u64 t; cvta.to.shared.u64 t, %1; cvt.u32.u64 %0, t; }" : "=r"(a) : "l"(p));
    return a;
}
__device__ __forceinline__ uint32_t f2tf(float f) {
    uint32_t u;
    asm("cvt.rna.tf32.f32 %0, %1;" : "=r"(u) : "f"(f));
    return u;
}
__device__ __forceinline__ void mbar_init(uint32_t a, uint32_t cnt) {
    asm volatile("mbarrier.init.shared.b64 [%0], %1;" :: "r"(a), "r"(cnt) : "memory");
}
__device__ __forceinline__ void mbar_arrive(uint32_t a) {
    asm volatile("mbarrier.arrive.shared.b64 _, [%0];" :: "r"(a) : "memory");
}
__device__ __forceinline__ void mbar_wait(uint32_t a, uint32_t parity) {
    uint32_t done;
    asm volatile(
        "{\n\t.reg .pred p;\n\t"
        "mbarrier.try_wait.parity.acquire.cta.shared::cta.b64 p, [%1], %2;\n\t"
        "selp.b32 %0, 1, 0, p;\n\t}"
        : "=r"(done) : "r"(a), "r"(parity) : "memory");
    if (!done) {
        asm volatile(
            "{\n\t.reg .pred P1;\n\t"
            "W_%=:\n\t"
            "mbarrier.try_wait.parity.acquire.cta.shared::cta.b64 P1, [%0], %1, 0x989680;\n\t"
            "@P1 bra.uni D_%=;\n\t"
            "bra.uni W_%=;\n\t"
            "D_%=:\n\t}"
            :: "r"(a), "r"(parity) : "memory");
    }
}
__device__ __forceinline__ void mma_tf32(float (&c)[4], const uint32_t (&a)[4],
                                         const uint32_t (&b)[2]) {
    asm volatile(
        "mma.sync.aligned.m16n8k8.row.col.f32.tf32.tf32.f32 "
        "{%0,%1,%2,%3}, {%4,%5,%6,%7}, {%8,%9}, {%0,%1,%2,%3};"
        : "+f"(c[0]), "+f"(c[1]), "+f"(c[2]), "+f"(c[3])
        : "r"(a[0]), "r"(a[1]), "r"(a[2]), "r"(a[3]), "r"(b[0]), "r"(b[1]));
}

// ---------------- init ----------------
__global__ void init_kernel(float* out_tail, int tail_n) {
    int t = blockIdx.x * blockDim.x + threadIdx.x;
    if (t < NEXP) g_cnt[t] = 0;
    if (t < tail_n) out_tail[t] = 0.0f;
}

// ---------------- router (unchanged — passing) ----------------
__global__ void __launch_bounds__(256) router_kernel(
    const float* __restrict__ x, const float* __restrict__ rw,
    const float* __restrict__ rb)
{
    __shared__ float s_w[NEXP][256];
    __shared__ float s_x[8][256];
    const int tid  = threadIdx.x;
    const int wid  = tid >> 5, lane = tid & 31;
    const int tok0 = blockIdx.x * 8;

    float acc[NEXP];
#pragma unroll
    for (int e = 0; e < NEXP; e++) acc[e] = 0.f;

    for (int ch = 0; ch < DIM / 256; ch++) {
        __syncthreads();
#pragma unroll
        for (int i = 0; i < 2; i++) {
            int f = tid + i * 256;
            int r = f >> 6, c = f & 63;
            ((float4*)&s_w[r][0])[c] =
                *(const float4*)(rw + (size_t)r * DIM + ch * 256 + c * 4);
            ((float4*)&s_x[r][0])[c] =
                *(const float4*)(x + (size_t)(tok0 + r) * DIM + ch * 256 + c * 4);
        }
        __syncthreads();
#pragma unroll
        for (int j = 0; j < 2; j++) {
            float4 xv = ((const float4*)&s_x[wid][0])[j * 32 + lane];
#pragma unroll
            for (int e = 0; e < NEXP; e++) {
                float4 wv = ((const float4*)&s_w[e][0])[j * 32 + lane];
                acc[e] += xv.x * wv.x + xv.y * wv.y + xv.z * wv.z + xv.w * wv.w;
            }
        }
    }
#pragma unroll
    for (int e = 0; e < NEXP; e++) {
        float v = acc[e];
#pragma unroll
        for (int o = 16; o > 0; o >>= 1) v += __shfl_xor_sync(0xffffffffu, v, o);
        acc[e] = v;
    }
    if (lane == 0) {
        int tok = tok0 + wid;
        float l[NEXP];
        float best = -3.4e38f;
        int bi = 0;
#pragma unroll
        for (int e = 0; e < NEXP; e++) {
            l[e] = acc[e] + rb[e];
            if (l[e] > best) { best = l[e]; bi = e; }
        }
        float denom = 0.f;
#pragma unroll
        for (int e = 0; e < NEXP; e++) denom += expf(l[e] - best);
        g_gate[tok] = 1.0f / denom;
        int pos = atomicAdd(&g_cnt[bi], 1);
        g_idx[bi * N_TOK + pos] = tok;
    }
}

// ---------------- warp-specialized grouped expert GEMM (mma.sync tf32) ----------------
// Warps 0-3: compute, 64x64 warp tiles over the 128x128 CTA tile.
// Warps 4-7: producers, LDG.128 -> cvt.rna.tf32 -> swizzled STS.128, 4-stage mbarrier ring.
__global__ void __launch_bounds__(256, 1) moe_gemm_kernel(
    const float* __restrict__ x, const float* __restrict__ ew,
    const float* __restrict__ eb, float* __restrict__ out)
{
    const int e   = blockIdx.z;
    const int cnt = g_cnt[e];
    const int m0  = blockIdx.y * BM;
    if (m0 >= cnt) return;
    const int n0  = blockIdx.x * BN;

    extern __shared__ char smem_raw[];
    __shared__ int s_tok[BM];

    const uint32_t u32raw = smem_u32(smem_raw);
    const uint32_t u32al  = (u32raw + 1023u) & ~1023u;
    char* smem = smem_raw + (u32al - u32raw);
    const uint32_t mb_full  = u32al + 0;     // ST barriers, 8B apart
    const uint32_t mb_empty = u32al + 64;
    char* tiles = smem + CTRL;

    const int tid  = threadIdx.x;
    const int wid  = tid >> 5;
    const int lane = tid & 31;
    const int gid  = lane >> 2;   // 0..7
    const int tig  = lane & 3;    // 0..3

    if (tid == 0) {
#pragma unroll
        for (int s = 0; s < ST; s++) {
            mbar_init(mb_full + s * 8, 128);   // 128 producer threads
            mbar_init(mb_empty + s * 8, 128);  // 128 compute threads
        }
    }
    if (tid < BM) {
        int row  = m0 + tid;
        int srow = (row < cnt) ? row : (cnt - 1);
        s_tok[tid] = g_idx[e * N_TOK + srow];
    }
    __syncthreads();

    if (wid >= 4) {
        // ================= producers =================
        const int t = tid - 128;               // 0..127
        const float* p[16];
        uint32_t d_off[16];
#pragma unroll
        for (int i = 0; i < 16; i++) {
            int f = i * 128 + t;               // 0..2047 16B-chunk id
            if (f < 1024) {                    // A: row r, chunk c4
                int r = f >> 3, c4 = f & 7;
                p[i] = x + (size_t)s_tok[r] * DIM + c4 * 4;
                d_off[i] = (uint32_t)(r * 128 + ((c4 ^ (r & 7)) << 4));
            } else {                           // B
                int g = f - 1024;
                int r = g >> 3, c4 = g & 7;
                p[i] = ew + (size_t)e * DIM * DIM + (size_t)(n0 + r) * DIM + c4 * 4;
                d_off[i] = (uint32_t)(A_BYTES + r * 128 + ((c4 ^ (r & 7)) << 4));
            }
        }
        uint32_t ph = 1;                       // first empty-wait passes
        for (int kt = 0; kt < KT; kt++) {
            int st = kt & (ST - 1);
            mbar_wait(mb_empty + st * 8, ph);
            char* tb = tiles + st * STAGE_BYTES;
            float4 v[16];
#pragma unroll
            for (int i = 0; i < 16; i++) v[i] = *(const float4*)(p[i] + kt * BK);
#pragma unroll
            for (int i = 0; i < 16; i++) {
                uint4 u = make_uint4(f2tf(v[i].x), f2tf(v[i].y), f2tf(v[i].z), f2tf(v[i].w));
                *(uint4*)(tb + d_off[i]) = u;
            }
            mbar_arrive(mb_full + st * 8);     // arrive = release; consumer wait = acquire
            if (st == ST - 1) ph ^= 1;
        }
        return;                                // producers done
    }

    // ================= compute: warp tile 64x64, 2x2 warp grid =================
    const int wm = wid & 1;                    // row half
    const int wn = wid >> 1;                   // col half

    float acc[4][8][4];
#pragma unroll
    for (int mi = 0; mi < 4; mi++)
#pragma unroll
        for (int ni = 0; ni < 8; ni++)
#pragma unroll
            for (int q = 0; q < 4; q++) acc[mi][ni][q] = 0.f;

    // row byte-offsets (A region) and col byte-offsets (B region)
    uint32_t rA[4], cB[8];
#pragma unroll
    for (int mi = 0; mi < 4; mi++) rA[mi] = (uint32_t)((wm * 64 + mi * 16 + gid) * 128);
#pragma unroll
    for (int ni = 0; ni < 8; ni++) cB[ni] = (uint32_t)(A_BYTES + (wn * 64 + ni * 8 + gid) * 128);

    uint32_t ph = 0;
    for (int kt = 0; kt < KT; kt++) {
        int st = kt & (ST - 1);
        mbar_wait(mb_full + st * 8, ph);
        const char* tb = tiles + st * STAGE_BYTES;
#pragma unroll
        for (int kk = 0; kk < BK; kk += 8) {
            // swizzled column byte offsets for words kk+tig and kk+tig+4
            const uint32_t col0 = ((((kk >> 2) + 0) ^ gid) << 4) | (tig << 2);
            const uint32_t col1 = ((((kk >> 2) + 1) ^ gid) << 4) | (tig << 2);
            uint32_t a[4][4];
            uint32_t b[8][2];
#pragma unroll
            for (int mi = 0; mi < 4; mi++) {
                a[mi][0] = *(const uint32_t*)(tb + rA[mi] + col0);
                a[mi][1] = *(const uint32_t*)(tb + rA[mi] + 1024 + col0);  // +8 rows
                a[mi][2] = *(const uint32_t*)(tb + rA[mi] + col1);
                a[mi][3] = *(const uint32_t*)(tb + rA[mi] + 1024 + col1);
            }
#pragma unroll
            for (int ni = 0; ni < 8; ni++) {
                b[ni][0] = *(const uint32_t*)(tb + cB[ni] + col0);
                b[ni][1] = *(const uint32_t*)(tb + cB[ni] + col1);
            }
#pragma unroll
            for (int mi = 0; mi < 4; mi++)
#pragma unroll
                for (int ni = 0; ni < 8; ni++)
                    mma_tf32(acc[mi][ni], a[mi], b[ni]);
        }
        mbar_arrive(mb_empty + st * 8);
        if (st == ST - 1) ph ^= 1;
    }

    // ================= epilogue: bias + gate + scatter =================
#pragma unroll
    for (int mi = 0; mi < 4; mi++) {
#pragma unroll
        for (int h = 0; h < 2; h++) {
            int r   = wm * 64 + mi * 16 + h * 8 + gid;
            int row = m0 + r;
            if (row >= cnt) continue;
            int tok    = s_tok[r];
            float gate = g_gate[tok];
            float* orow       = out + (size_t)tok * DIM + n0 + wn * 64;
            const float* brow = eb + (size_t)e * DIM + n0 + wn * 64;
#pragma unroll
            for (int ni = 0; ni < 8; ni++) {
                int c = ni * 8 + tig * 2;
                float v0 = (acc[mi][ni][h * 2 + 0] + brow[c]) * gate;
                float v1 = (acc[mi][ni][h * 2 + 1] + brow[c + 1]) * gate;
                *(float2*)(orow + c) = make_float2(v0, v1);
            }
        }
    }
}

// ---------------- launch ----------------
extern "C" void kernel_launch(void* const* d_in, const int* in_sizes, int n_in,
                              void* d_out, int out_size) {
    const float* x  = (const float*)d_in[0];   // [8192, 2048]
    const float* ew = (const float*)d_in[1];   // [8, 2048, 2048]
    const float* eb = (const float*)d_in[2];   // [8, 2048]
    const float* rw = (const float*)d_in[3];   // [8, 2048]
    const float* rb = (const float*)d_in[4];   // [8]
    float* out = (float*)d_out;

    cudaFuncSetAttribute(moe_gemm_kernel,
                         cudaFuncAttributeMaxDynamicSharedMemorySize, SMEM_DYN);

    int tail = out_size - N_TOK * DIM;
    if (tail < 0) tail = 0;
    init_kernel<<<1, 256>>>(out + N_TOK * DIM, tail);

    router_kernel<<<N_TOK / 8, 256>>>(x, rw, rb);

    dim3 grid(DIM / BN, N_TOK / BM, NEXP);
    moe_gemm_kernel<<<grid, 256, SMEM_DYN>>>(x, ew, eb, out);
}